// round 7
// baseline (speedup 1.0000x reference)
#include <cuda_runtime.h>
#include <math.h>

#define N_ENT 100000
#define N_REL 64
#define E_DIM 64
#define KNB   32
#define BSZ   1024

typedef unsigned long long ull;

// Device scratch (no allocation allowed)
__device__ float  d_scale[N_ENT];            // per-entity normalization scale
__device__ float  d_RW[N_REL * E_DIM];       // RW[rel][f] = Rnorm[rel] . w1r[f]
__device__ float2 d_W2P[E_DIM * 32];         // d_W2P[f*32+q] = (w2[q][f], w2[q+32][f])

__device__ __forceinline__ float leaky(float x) { return x >= 0.f ? x : 0.2f * x; }

__device__ __forceinline__ ull ffma2(ull a, ull b, ull c) {
    ull d;
    asm("fma.rn.f32x2 %0, %1, %2, %3;" : "=l"(d) : "l"(a), "l"(b), "l"(c));
    return d;
}
__device__ __forceinline__ ull packdup(float x) {
    ull d;
    asm("mov.b64 %0, {%1, %1};" : "=l"(d) : "f"(x));
    return d;
}

// ---------------------------------------------------------------------------
// prep kernel: blocks [0, NB_NORM) compute per-entity scales; last block
// normalizes R, builds RW and pre-pairs W2.
// ---------------------------------------------------------------------------
#define ROWS_PER_BLK 32
#define NB_NORM ((N_ENT + ROWS_PER_BLK - 1) / ROWS_PER_BLK)

__global__ void __launch_bounds__(256) prep_kernel(const float* __restrict__ E,
                                                   const float* __restrict__ R,
                                                   const float* __restrict__ w1,
                                                   const float* __restrict__ w2) {
    int tid = threadIdx.x, w = tid >> 5, lane = tid & 31;

    if (blockIdx.x < NB_NORM) {
        int l = tid & 15;
        int rg = tid >> 4;
        int rowA = blockIdx.x * ROWS_PER_BLK + rg;
        int rowB = rowA + 16;
        float4 vA = make_float4(0, 0, 0, 0), vB = make_float4(0, 0, 0, 0);
        if (rowA < N_ENT) vA = ((const float4*)(E + (size_t)rowA * E_DIM))[l];
        if (rowB < N_ENT) vB = ((const float4*)(E + (size_t)rowB * E_DIM))[l];
        float sA = vA.x * vA.x + vA.y * vA.y + vA.z * vA.z + vA.w * vA.w;
        float sB = vB.x * vB.x + vB.y * vB.y + vB.z * vB.z + vB.w * vB.w;
        #pragma unroll
        for (int o = 8; o > 0; o >>= 1) {
            sA += __shfl_xor_sync(0xffffffffu, sA, o);
            sB += __shfl_xor_sync(0xffffffffu, sB, o);
        }
        if (l == 0) {
            if (rowA < N_ENT) {
                float n = sqrtf(sA);
                d_scale[rowA] = (n > 1.0f) ? 1.0f / (n + 1e-7f) : 1.0f;
            }
            if (rowB < N_ENT) {
                float n = sqrtf(sB);
                d_scale[rowB] = (n > 1.0f) ? 1.0f / (n + 1e-7f) : 1.0f;
            }
        }
        return;
    }

    // ---- prepRW block ----
    __shared__ float Rn[N_REL * E_DIM];       // 16 KB
    __shared__ float w1rT[E_DIM * 65];
    #pragma unroll
    for (int k = 0; k < 8; k++) {
        int row = w * 8 + k;
        float2 v = ((const float2*)(R + row * E_DIM))[lane];
        float ss = v.x * v.x + v.y * v.y;
        #pragma unroll
        for (int o = 16; o > 0; o >>= 1) ss += __shfl_xor_sync(0xffffffffu, ss, o);
        float n = sqrtf(ss);
        float sc = (n > 1.0f) ? 1.0f / (n + 1e-7f) : 1.0f;
        Rn[row * E_DIM + lane * 2]     = v.x * sc;
        Rn[row * E_DIM + lane * 2 + 1] = v.y * sc;
    }
    for (int i = tid; i < E_DIM * E_DIM; i += 256) {
        int f = i >> 6, e = i & 63;
        w1rT[e * 65 + f] = w1[f * 128 + 64 + e];
    }
    #pragma unroll
    for (int j = 0; j < 8; j++) {
        int i = tid + j * 256;               // i = f*32+q
        int f = i >> 5, q = i & 31;
        d_W2P[i] = make_float2(w2[q * E_DIM + f], w2[(q + 32) * E_DIM + f]);
    }
    __syncthreads();
    #pragma unroll
    for (int j = 0; j < 16; j++) {
        int i = tid + j * 256;
        int rel = i >> 6, f = i & 63;
        float s = 0.f;
        #pragma unroll
        for (int e = 0; e < E_DIM; e++) s += Rn[rel * E_DIM + e] * w1rT[e * 65 + f];
        d_RW[rel * E_DIM + f] = s;
    }
}

// ---------------------------------------------------------------------------
// Fused per-root kernel. One block (256 threads) per root.
// __launch_bounds__(256,5): <=51 regs -> 5 CTAs/SM (reg-limited occupancy fix).
// hidAll staged ONCE for all 64 f (24 KB, unioned with later scratch);
// score-GEMM runs in 2 o-pair halves of 6 accumulators each.
// Entries: 0..31 = hop-1 neighbors (query hWh), 32..95 = hop-2 rels (hWs).
// big[] union timeline (ordered by __syncthreads):
//   hidAll [0..6144) -> scoreP [0..768) -> wS [768..1792) + part [1792..2880)
// ---------------------------------------------------------------------------
__global__ void __launch_bounds__(256, 5) fused_kernel(
        const int* __restrict__ entity_idx,
        const int* __restrict__ adj_e,
        const int* __restrict__ adj_r,
        const float* __restrict__ E,
        const float* __restrict__ w1,
        const float* __restrict__ w3,
        const float* __restrict__ wxw,
        const float* __restrict__ wxb,
        const float* __restrict__ wcw,
        const float* __restrict__ wcb,
        float* __restrict__ out) {
    int b = blockIdx.x;
    int tid = threadIdx.x, w = tid >> 5, lane = tid & 31;

    __shared__ float  t1[KNB * E_DIM];          // 8 KB
    __shared__ int    idx2[KNB * KNB];          // 4 KB: idx | (rel<<20)
    __shared__ float  big[6144];                // 24 KB union
    __shared__ float  eaAll[96];
    __shared__ float  hS[E_DIM], hsumS[E_DIM];
    __shared__ float  hWh[E_DIM], hWs[E_DIM];
    __shared__ float  aggS[E_DIM], vS[E_DIM];
    __shared__ int    ent1[KNB], rel1[KNB];
    __shared__ float  red8[8];
    __shared__ float  sS1, sS2;

    float* hidAll = big;                        // [0..6144), pitch 96, 64 rows
    float* scoreP = big;                        // [0..768), 8*96
    float* wS     = big + 768;                  // [768..1792)
    float* part   = big + 1792;                 // [1792..2880), 16*68

    int eidx = entity_idx[b];
    // ---- Phase A: root loads ----
    if (tid < KNB) {
        ent1[tid] = adj_e[eidx * KNB + tid];
        rel1[tid] = adj_r[eidx * KNB + tid];
    }
    if (tid < E_DIM) hS[tid] = E[(size_t)eidx * E_DIM + tid] * __ldg(&d_scale[eidx]);
    __syncthreads();

    // ---- Phase B: hop-2 packed indices + normalized t1 rows ----
    for (int i = tid; i < KNB * KNB; i += 256) {
        int e1 = ent1[i >> 5];
        int id = adj_e[e1 * KNB + (i & 31)];
        int rl = adj_r[e1 * KNB + (i & 31)];
        idx2[i] = id | (rl << 20);
    }
    for (int i = tid; i < KNB * E_DIM; i += 256) {
        int n = i >> 6, e = i & 63;
        int id = ent1[n];
        t1[i] = E[(size_t)id * E_DIM + e] * __ldg(&d_scale[id]);
    }
    __syncthreads();

    // ---- hsum ----
    if (tid < E_DIM) {
        float s = 0.f;
        #pragma unroll
        for (int n = 0; n < KNB; n++) s += t1[n * E_DIM + tid];
        hsumS[tid] = s;
    }
    __syncthreads();

    // ---- query projections ----
    #pragma unroll
    for (int k = 0; k < 16; k++) {
        int job = w * 16 + k;
        int f = job & 63;
        const float* q = (job < 64) ? hS : hsumS;
        float2 wv = ((const float2*)(w1 + f * 128))[lane];
        float p = wv.x * q[lane * 2] + wv.y * q[lane * 2 + 1];
        #pragma unroll
        for (int o = 16; o > 0; o >>= 1) p += __shfl_down_sync(0xffffffffu, p, o);
        if (lane == 0) { if (job < 64) hWh[f] = p; else hWs[f] = p; }
    }
    __syncthreads();

    // ---- stage hidAll for ALL 64 f: hidAll[f*96+entry] = relu(q[f]+RW[rel][f])
    if (tid < 192) {
        int entry = tid >> 1, fh = tid & 1;
        int rel = (entry < KNB) ? rel1[entry] : (entry - KNB);
        const float* qv = (entry < KNB) ? hWh : hWs;
        #pragma unroll
        for (int j = 0; j < 32; j++) {
            int f = fh * 32 + j;
            float x = qv[f] + __ldg(&d_RW[rel * E_DIM + f]);
            hidAll[f * 96 + entry] = x > 0.f ? x : 0.f;
        }
    }
    __syncthreads();

    // ---- score GEMM: 2 o-pair halves, 6 packed accumulators each ----
    float sPart0 = 0.f, sPart1 = 0.f, sPart2 = 0.f;
    {
        const ull* W2u = (const ull*)d_W2P;
        int e0 = lane * 3;
        #pragma unroll
        for (int half = 0; half < 2; half++) {
            ull a00 = 0, a01 = 0, a02 = 0, a10 = 0, a11 = 0, a12 = 0;
            int ob = w * 4 + half * 2;
            #pragma unroll 16
            for (int f = 0; f < E_DIM; f++) {
                ull wa = __ldg(&W2u[f * 32 + ob + 0]);
                ull wb = __ldg(&W2u[f * 32 + ob + 1]);
                ull h0 = packdup(hidAll[f * 96 + e0]);
                ull h1 = packdup(hidAll[f * 96 + e0 + 1]);
                ull h2 = packdup(hidAll[f * 96 + e0 + 2]);
                a00 = ffma2(wa, h0, a00);
                a01 = ffma2(wa, h1, a01);
                a02 = ffma2(wa, h2, a02);
                a10 = ffma2(wb, h0, a10);
                a11 = ffma2(wb, h1, a11);
                a12 = ffma2(wb, h2, a12);
            }
            float wlo0 = __ldg(&w3[ob]),     whi0 = __ldg(&w3[ob + 32]);
            float wlo1 = __ldg(&w3[ob + 1]), whi1 = __ldg(&w3[ob + 33]);
            #pragma unroll
            for (int j = 0; j < 3; j++) {
                ull aA = (j == 0) ? a00 : (j == 1) ? a01 : a02;
                ull aB = (j == 0) ? a10 : (j == 1) ? a11 : a12;
                float g0 = __uint_as_float((unsigned)(aA & 0xffffffffull));
                float g1 = __uint_as_float((unsigned)(aA >> 32));
                float g2 = __uint_as_float((unsigned)(aB & 0xffffffffull));
                float g3 = __uint_as_float((unsigned)(aB >> 32));
                g0 = g0 > 0.f ? g0 : 0.f;
                g1 = g1 > 0.f ? g1 : 0.f;
                g2 = g2 > 0.f ? g2 : 0.f;
                g3 = g3 > 0.f ? g3 : 0.f;
                float s = wlo0 * g0 + whi0 * g1 + wlo1 * g2 + whi1 * g3;
                if (j == 0) sPart0 += s; else if (j == 1) sPart1 += s; else sPart2 += s;
            }
        }
    }
    __syncthreads();   // hidAll dead; scoreP region reuse
    {
        int e0 = lane * 3;
        scoreP[w * 96 + e0]     = sPart0;
        scoreP[w * 96 + e0 + 1] = sPart1;
        scoreP[w * 96 + e0 + 2] = sPart2;
    }
    __syncthreads();
    if (tid < 96) {
        float c = 0.f;
        #pragma unroll
        for (int ww = 0; ww < 8; ww++) c += scoreP[ww * 96 + tid];
        eaAll[tid] = expf(1.f / (1.f + expf(-c)));
    }
    __syncthreads();

    // ---- per-neighbor weights wS[n] = ea[rel]*scale[idx]; S2 = sum ea ----
    {
        float sp = 0.f;
        #pragma unroll
        for (int j = 0; j < 4; j++) {
            int i = tid * 4 + j;
            int v = idx2[i];
            int rl = v >> 20, id = v & 0xFFFFF;
            float ea = eaAll[32 + rl];
            wS[i] = ea * __ldg(&d_scale[id]);
            sp += ea;
        }
        #pragma unroll
        for (int o = 16; o > 0; o >>= 1) sp += __shfl_down_sync(0xffffffffu, sp, o);
        if (lane == 0) red8[w] = sp;
    }
    __syncthreads();
    if (tid == 0) {
        float s = 0.f;
        #pragma unroll
        for (int i = 0; i < 8; i++) s += red8[i];
        sS2 = s;
    }
    __syncthreads();

    // ---- hop-2 weighted gather (unroll 4, low reg pressure) ----
    {
        const float4* E4 = (const float4*)E;
        int seg = tid & 15, r = tid >> 4;
        float4 gacc = make_float4(0.f, 0.f, 0.f, 0.f);
        #pragma unroll
        for (int base = 0; base < KNB * KNB; base += 64) {
            int   ids[4];
            float ws[4];
            float4 vs[4];
            #pragma unroll
            for (int u4 = 0; u4 < 4; u4++) {
                int n = base + u4 * 16 + r;
                ids[u4] = idx2[n] & 0xFFFFF;
                ws[u4] = wS[n];
            }
            #pragma unroll
            for (int u4 = 0; u4 < 4; u4++)
                vs[u4] = __ldg(&E4[(size_t)ids[u4] * 16 + seg]);
            #pragma unroll
            for (int u4 = 0; u4 < 4; u4++) {
                gacc.x += ws[u4] * vs[u4].x; gacc.y += ws[u4] * vs[u4].y;
                gacc.z += ws[u4] * vs[u4].z; gacc.w += ws[u4] * vs[u4].w;
            }
        }
        ((float4*)(part + r * 68))[seg] = gacc;
    }

    // ---- hop-1 aggregation ----
    if (tid < E_DIM) {
        float ag = 0.f;
        #pragma unroll
        for (int n = 0; n < KNB; n++) ag += eaAll[n] * t1[n * E_DIM + tid];
        aggS[tid] = ag;
    }
    if (tid >= 64 && tid < 96) {
        int l2 = tid - 64;
        float e = eaAll[l2];
        #pragma unroll
        for (int o = 16; o > 0; o >>= 1) e += __shfl_down_sync(0xffffffffu, e, o);
        if (l2 == 0) sS1 = e;
    }
    __syncthreads();
    if (tid < E_DIM) aggS[tid] /= sS1;
    __syncthreads();

    // ---- hop-1 epilogue ----
    #pragma unroll
    for (int k = 0; k < 8; k++) {
        int o = w * 8 + k;
        float2 wv = ((const float2*)(wxw + o * E_DIM))[lane];
        float p = wv.x * aggS[lane * 2] + wv.y * aggS[lane * 2 + 1];
        #pragma unroll
        for (int off = 16; off > 0; off >>= 1) p += __shfl_down_sync(0xffffffffu, p, off);
        if (lane == 0) vS[o] = leaky(p + wxb[o]);
    }
    __syncthreads();
    #pragma unroll
    for (int k = 0; k < 8; k++) {
        int o = w * 8 + k;
        float4 wv = ((const float4*)(wcw + o * 128))[lane];
        int i0 = lane * 4;
        float x0 = (i0 < 64)     ? hS[i0]     : vS[i0 - 64];
        float x1 = (i0 + 1 < 64) ? hS[i0 + 1] : vS[i0 - 63];
        float x2 = (i0 + 2 < 64) ? hS[i0 + 2] : vS[i0 - 62];
        float x3 = (i0 + 3 < 64) ? hS[i0 + 3] : vS[i0 - 61];
        float p = wv.x * x0 + wv.y * x1 + wv.z * x2 + wv.w * x3;
        #pragma unroll
        for (int off = 16; off > 0; off >>= 1) p += __shfl_down_sync(0xffffffffu, p, off);
        if (lane == 0) out[b * 192 + 64 + o] = leaky(p + wcb[o]);
    }
    if (tid < E_DIM) out[b * 192 + 128 + tid] = hS[tid];
    __syncthreads();

    // ---- hop-2 epilogue ----
    if (tid < E_DIM) {
        float s = 0.f;
        #pragma unroll
        for (int r = 0; r < 16; r++) s += part[r * 68 + tid];
        aggS[tid] = s / sS2;
    }
    __syncthreads();
    #pragma unroll
    for (int k = 0; k < 8; k++) {
        int o = w * 8 + k;
        float2 wv = ((const float2*)(wxw + o * E_DIM))[lane];
        float p = wv.x * aggS[lane * 2] + wv.y * aggS[lane * 2 + 1];
        #pragma unroll
        for (int off = 16; off > 0; off >>= 1) p += __shfl_down_sync(0xffffffffu, p, off);
        if (lane == 0) vS[o] = leaky(p + wxb[o]);
    }
    __syncthreads();
    #pragma unroll
    for (int k = 0; k < 8; k++) {
        int o = w * 8 + k;
        float4 wv = ((const float4*)(wcw + o * 128))[lane];
        int i0 = lane * 4;
        float x0 = (i0 < 64)     ? hsumS[i0]     : vS[i0 - 64];
        float x1 = (i0 + 1 < 64) ? hsumS[i0 + 1] : vS[i0 - 63];
        float x2 = (i0 + 2 < 64) ? hsumS[i0 + 2] : vS[i0 - 62];
        float x3 = (i0 + 3 < 64) ? hsumS[i0 + 3] : vS[i0 - 61];
        float p = wv.x * x0 + wv.y * x1 + wv.z * x2 + wv.w * x3;
        #pragma unroll
        for (int off = 16; off > 0; off >>= 1) p += __shfl_down_sync(0xffffffffu, p, off);
        if (lane == 0) out[b * 192 + o] = leaky(p + wcb[o]);
    }
}

// ---------------------------------------------------------------------------
extern "C" void kernel_launch(void* const* d_in, const int* in_sizes, int n_in,
                              void* d_out, int out_size) {
    const int*   entity_idx = (const int*)d_in[0];
    const int*   adj_e      = (const int*)d_in[1];
    const int*   adj_r      = (const int*)d_in[2];
    const float* E          = (const float*)d_in[3];
    const float* R          = (const float*)d_in[4];
    const float* w1         = (const float*)d_in[5];
    const float* w2         = (const float*)d_in[6];
    const float* w3         = (const float*)d_in[7];
    const float* wxw        = (const float*)d_in[8];
    const float* wxb        = (const float*)d_in[9];
    const float* wcw        = (const float*)d_in[10];
    const float* wcb        = (const float*)d_in[11];
    float* out = (float*)d_out;

    prep_kernel<<<NB_NORM + 1, 256>>>(E, R, w1, w2);
    fused_kernel<<<BSZ, 256>>>(entity_idx, adj_e, adj_r, E, w1, w3,
                               wxw, wxb, wcw, wcb, out);
}

// round 8
// speedup vs baseline: 1.3044x; 1.3044x over previous
#include <cuda_runtime.h>
#include <math.h>

#define N_ENT 100000
#define N_REL 64
#define E_DIM 64
#define KNB   32
#define BSZ   1024

typedef unsigned long long ull;

// Device scratch (no allocation allowed)
__device__ float  d_scale[N_ENT];            // per-entity normalization scale
__device__ float  d_RW[N_REL * E_DIM];       // RW[rel][f] = Rnorm[rel] . w1r[f]
__device__ float2 d_W2P[E_DIM * 32];         // d_W2P[f*32+q] = (w2[q][f], w2[q+32][f])

__device__ __forceinline__ float leaky(float x) { return x >= 0.f ? x : 0.2f * x; }

__device__ __forceinline__ ull ffma2(ull a, ull b, ull c) {
    ull d;
    asm("fma.rn.f32x2 %0, %1, %2, %3;" : "=l"(d) : "l"(a), "l"(b), "l"(c));
    return d;
}
__device__ __forceinline__ ull packdup(float x) {
    ull d;
    asm("mov.b64 %0, {%1, %1};" : "=l"(d) : "f"(x));
    return d;
}

// ---------------------------------------------------------------------------
// prep kernel: blocks [0, NB_NORM) compute per-entity scales; last block
// normalizes R, builds RW and pre-pairs W2.
// ---------------------------------------------------------------------------
#define ROWS_PER_BLK 32
#define NB_NORM ((N_ENT + ROWS_PER_BLK - 1) / ROWS_PER_BLK)

__global__ void __launch_bounds__(256) prep_kernel(const float* __restrict__ E,
                                                   const float* __restrict__ R,
                                                   const float* __restrict__ w1,
                                                   const float* __restrict__ w2) {
    int tid = threadIdx.x, w = tid >> 5, lane = tid & 31;

    if (blockIdx.x < NB_NORM) {
        int l = tid & 15;
        int rg = tid >> 4;
        int rowA = blockIdx.x * ROWS_PER_BLK + rg;
        int rowB = rowA + 16;
        float4 vA = make_float4(0, 0, 0, 0), vB = make_float4(0, 0, 0, 0);
        if (rowA < N_ENT) vA = ((const float4*)(E + (size_t)rowA * E_DIM))[l];
        if (rowB < N_ENT) vB = ((const float4*)(E + (size_t)rowB * E_DIM))[l];
        float sA = vA.x * vA.x + vA.y * vA.y + vA.z * vA.z + vA.w * vA.w;
        float sB = vB.x * vB.x + vB.y * vB.y + vB.z * vB.z + vB.w * vB.w;
        #pragma unroll
        for (int o = 8; o > 0; o >>= 1) {
            sA += __shfl_xor_sync(0xffffffffu, sA, o);
            sB += __shfl_xor_sync(0xffffffffu, sB, o);
        }
        if (l == 0) {
            if (rowA < N_ENT) {
                float n = sqrtf(sA);
                d_scale[rowA] = (n > 1.0f) ? 1.0f / (n + 1e-7f) : 1.0f;
            }
            if (rowB < N_ENT) {
                float n = sqrtf(sB);
                d_scale[rowB] = (n > 1.0f) ? 1.0f / (n + 1e-7f) : 1.0f;
            }
        }
        return;
    }

    // ---- prepRW block ----
    __shared__ float Rn[N_REL * E_DIM];       // 16 KB
    __shared__ float w1rT[E_DIM * 65];
    #pragma unroll
    for (int k = 0; k < 8; k++) {
        int row = w * 8 + k;
        float2 v = ((const float2*)(R + row * E_DIM))[lane];
        float ss = v.x * v.x + v.y * v.y;
        #pragma unroll
        for (int o = 16; o > 0; o >>= 1) ss += __shfl_xor_sync(0xffffffffu, ss, o);
        float n = sqrtf(ss);
        float sc = (n > 1.0f) ? 1.0f / (n + 1e-7f) : 1.0f;
        Rn[row * E_DIM + lane * 2]     = v.x * sc;
        Rn[row * E_DIM + lane * 2 + 1] = v.y * sc;
    }
    for (int i = tid; i < E_DIM * E_DIM; i += 256) {
        int f = i >> 6, e = i & 63;
        w1rT[e * 65 + f] = w1[f * 128 + 64 + e];
    }
    #pragma unroll
    for (int j = 0; j < 8; j++) {
        int i = tid + j * 256;               // i = f*32+q
        int f = i >> 5, q = i & 31;
        d_W2P[i] = make_float2(w2[q * E_DIM + f], w2[(q + 32) * E_DIM + f]);
    }
    __syncthreads();
    #pragma unroll
    for (int j = 0; j < 16; j++) {
        int i = tid + j * 256;
        int rel = i >> 6, f = i & 63;
        float s = 0.f;
        #pragma unroll
        for (int e = 0; e < E_DIM; e++) s += Rn[rel * E_DIM + e] * w1rT[e * 65 + f];
        d_RW[rel * E_DIM + f] = s;
    }
}

// ---------------------------------------------------------------------------
// Fused per-root kernel. One block (256 threads) per root.
// L1-wavefront-minimized:
//  - hid staging via float4 RW loads (entry,seg jobs), hidAll pitch 97
//  - score GEMM single pass, 12 packed accums, W2 via 2x LDG.128 broadcast/f
// Entries: 0..31 = hop-1 neighbors (query hWh), 32..95 = hop-2 rels (hWs).
// big[] union (ordered by __syncthreads):
//   hidAll [0..6208) -> scoreP [0..768) -> wS [768..1792) + part [1792..2880)
// ---------------------------------------------------------------------------
__global__ void __launch_bounds__(256, 4) fused_kernel(
        const int* __restrict__ entity_idx,
        const int* __restrict__ adj_e,
        const int* __restrict__ adj_r,
        const float* __restrict__ E,
        const float* __restrict__ w1,
        const float* __restrict__ w3,
        const float* __restrict__ wxw,
        const float* __restrict__ wxb,
        const float* __restrict__ wcw,
        const float* __restrict__ wcb,
        float* __restrict__ out) {
    int b = blockIdx.x;
    int tid = threadIdx.x, w = tid >> 5, lane = tid & 31;

    __shared__ float  t1[KNB * E_DIM];          // 8 KB
    __shared__ int    idx2[KNB * KNB];          // 4 KB: idx | (rel<<20)
    __shared__ float  big[6208];                // 24.8 KB union
    __shared__ float  eaAll[96];
    __shared__ float  hS[E_DIM], hsumS[E_DIM];
    __shared__ float  hWh[E_DIM], hWs[E_DIM];
    __shared__ float  aggS[E_DIM], vS[E_DIM];
    __shared__ int    ent1[KNB], rel1[KNB];
    __shared__ float  red8[8];
    __shared__ float  sS1, sS2;

    float* hidAll = big;                        // [0..6208), pitch 97, 64 f-rows
    float* scoreP = big;                        // [0..768), 8*96
    float* wS     = big + 768;                  // [768..1792)
    float* part   = big + 1792;                 // [1792..2880), 16*68

    int eidx = entity_idx[b];
    // ---- Phase A: root loads ----
    if (tid < KNB) {
        ent1[tid] = adj_e[eidx * KNB + tid];
        rel1[tid] = adj_r[eidx * KNB + tid];
    }
    if (tid < E_DIM) hS[tid] = E[(size_t)eidx * E_DIM + tid] * __ldg(&d_scale[eidx]);
    __syncthreads();

    // ---- Phase B: hop-2 packed indices + normalized t1 rows ----
    for (int i = tid; i < KNB * KNB; i += 256) {
        int e1 = ent1[i >> 5];
        int id = adj_e[e1 * KNB + (i & 31)];
        int rl = adj_r[e1 * KNB + (i & 31)];
        idx2[i] = id | (rl << 20);
    }
    for (int i = tid; i < KNB * E_DIM; i += 256) {
        int n = i >> 6, e = i & 63;
        int id = ent1[n];
        t1[i] = E[(size_t)id * E_DIM + e] * __ldg(&d_scale[id]);
    }
    __syncthreads();

    // ---- hsum ----
    if (tid < E_DIM) {
        float s = 0.f;
        #pragma unroll
        for (int n = 0; n < KNB; n++) s += t1[n * E_DIM + tid];
        hsumS[tid] = s;
    }
    __syncthreads();

    // ---- query projections ----
    #pragma unroll
    for (int k = 0; k < 16; k++) {
        int job = w * 16 + k;
        int f = job & 63;
        const float* q = (job < 64) ? hS : hsumS;
        float2 wv = ((const float2*)(w1 + f * 128))[lane];
        float p = wv.x * q[lane * 2] + wv.y * q[lane * 2 + 1];
        #pragma unroll
        for (int o = 16; o > 0; o >>= 1) p += __shfl_down_sync(0xffffffffu, p, o);
        if (lane == 0) { if (job < 64) hWh[f] = p; else hWs[f] = p; }
    }
    __syncthreads();

    // ---- stage hidAll via float4 RW loads: 1536 (entry,seg) jobs, 6/thread
    // hidAll[f*97+entry] = relu(q[f] + RW[rel][f])
    {
        const float4* RW4 = (const float4*)d_RW;
        #pragma unroll
        for (int j = 0; j < 6; j++) {
            int job = j * 256 + tid;            // coalesced: warp = 2 entries x 16 segs
            int entry = job >> 4, seg = job & 15;
            int rel = (entry < KNB) ? rel1[entry] : (entry - KNB);
            const float* qv = (entry < KNB) ? hWh : hWs;
            float4 rw = __ldg(&RW4[rel * 16 + seg]);
            int f0 = seg * 4;
            float x0 = qv[f0]     + rw.x;
            float x1 = qv[f0 + 1] + rw.y;
            float x2 = qv[f0 + 2] + rw.z;
            float x3 = qv[f0 + 3] + rw.w;
            hidAll[(f0)     * 97 + entry] = x0 > 0.f ? x0 : 0.f;
            hidAll[(f0 + 1) * 97 + entry] = x1 > 0.f ? x1 : 0.f;
            hidAll[(f0 + 2) * 97 + entry] = x2 > 0.f ? x2 : 0.f;
            hidAll[(f0 + 3) * 97 + entry] = x3 > 0.f ? x3 : 0.f;
        }
    }
    __syncthreads();

    // ---- score GEMM: single pass, 12 packed accums, W2 via 2x LDG.128/f ----
    float sPart0, sPart1, sPart2;
    {
        ull a[12];
        #pragma unroll
        for (int i = 0; i < 12; i++) a[i] = 0ull;
        const ulonglong2* W2q = (const ulonglong2*)d_W2P;  // [f*16 + q/2]
        int e0 = lane * 3;
        #pragma unroll 8
        for (int f = 0; f < E_DIM; f++) {
            ulonglong2 wab = __ldg(&W2q[f * 16 + w * 2]);      // o-pairs w*4+0, w*4+1
            ulonglong2 wcd = __ldg(&W2q[f * 16 + w * 2 + 1]);  // o-pairs w*4+2, w*4+3
            ull h0 = packdup(hidAll[f * 97 + e0]);
            ull h1 = packdup(hidAll[f * 97 + e0 + 1]);
            ull h2 = packdup(hidAll[f * 97 + e0 + 2]);
            a[0]  = ffma2(wab.x, h0, a[0]);
            a[1]  = ffma2(wab.x, h1, a[1]);
            a[2]  = ffma2(wab.x, h2, a[2]);
            a[3]  = ffma2(wab.y, h0, a[3]);
            a[4]  = ffma2(wab.y, h1, a[4]);
            a[5]  = ffma2(wab.y, h2, a[5]);
            a[6]  = ffma2(wcd.x, h0, a[6]);
            a[7]  = ffma2(wcd.x, h1, a[7]);
            a[8]  = ffma2(wcd.x, h2, a[8]);
            a[9]  = ffma2(wcd.y, h0, a[9]);
            a[10] = ffma2(wcd.y, h1, a[10]);
            a[11] = ffma2(wcd.y, h2, a[11]);
        }
        float w3v[4], w3u[4];
        #pragma unroll
        for (int q = 0; q < 4; q++) {
            int o = w * 4 + q;
            w3v[q] = __ldg(&w3[o]);
            w3u[q] = __ldg(&w3[o + 32]);
        }
        float sp[3];
        #pragma unroll
        for (int j = 0; j < 3; j++) {
            float s = 0.f;
            #pragma unroll
            for (int q = 0; q < 4; q++) {
                ull av = a[q * 3 + j];
                float g0 = __uint_as_float((unsigned)(av & 0xffffffffull));
                float g1 = __uint_as_float((unsigned)(av >> 32));
                g0 = g0 > 0.f ? g0 : 0.f;
                g1 = g1 > 0.f ? g1 : 0.f;
                s += w3v[q] * g0 + w3u[q] * g1;
            }
            sp[j] = s;
        }
        sPart0 = sp[0]; sPart1 = sp[1]; sPart2 = sp[2];
    }
    __syncthreads();   // hidAll dead; scoreP reuse
    {
        int e0 = lane * 3;
        scoreP[w * 96 + e0]     = sPart0;
        scoreP[w * 96 + e0 + 1] = sPart1;
        scoreP[w * 96 + e0 + 2] = sPart2;
    }
    __syncthreads();
    if (tid < 96) {
        float c = 0.f;
        #pragma unroll
        for (int ww = 0; ww < 8; ww++) c += scoreP[ww * 96 + tid];
        eaAll[tid] = expf(1.f / (1.f + expf(-c)));
    }
    __syncthreads();

    // ---- per-neighbor weights wS[n] = ea[rel]*scale[idx]; S2 = sum ea ----
    {
        float sp = 0.f;
        #pragma unroll
        for (int j = 0; j < 4; j++) {
            int i = tid * 4 + j;
            int v = idx2[i];
            int rl = v >> 20, id = v & 0xFFFFF;
            float ea = eaAll[32 + rl];
            wS[i] = ea * __ldg(&d_scale[id]);
            sp += ea;
        }
        #pragma unroll
        for (int o = 16; o > 0; o >>= 1) sp += __shfl_down_sync(0xffffffffu, sp, o);
        if (lane == 0) red8[w] = sp;
    }
    __syncthreads();
    if (tid == 0) {
        float s = 0.f;
        #pragma unroll
        for (int i = 0; i < 8; i++) s += red8[i];
        sS2 = s;
    }
    __syncthreads();

    // ---- hop-2 weighted gather (unroll 4) ----
    {
        const float4* E4 = (const float4*)E;
        int seg = tid & 15, r = tid >> 4;
        float4 gacc = make_float4(0.f, 0.f, 0.f, 0.f);
        #pragma unroll
        for (int base = 0; base < KNB * KNB; base += 64) {
            int   ids[4];
            float ws[4];
            float4 vs[4];
            #pragma unroll
            for (int u4 = 0; u4 < 4; u4++) {
                int n = base + u4 * 16 + r;
                ids[u4] = idx2[n] & 0xFFFFF;
                ws[u4] = wS[n];
            }
            #pragma unroll
            for (int u4 = 0; u4 < 4; u4++)
                vs[u4] = __ldg(&E4[(size_t)ids[u4] * 16 + seg]);
            #pragma unroll
            for (int u4 = 0; u4 < 4; u4++) {
                gacc.x += ws[u4] * vs[u4].x; gacc.y += ws[u4] * vs[u4].y;
                gacc.z += ws[u4] * vs[u4].z; gacc.w += ws[u4] * vs[u4].w;
            }
        }
        ((float4*)(part + r * 68))[seg] = gacc;
    }

    // ---- hop-1 aggregation ----
    if (tid < E_DIM) {
        float ag = 0.f;
        #pragma unroll
        for (int n = 0; n < KNB; n++) ag += eaAll[n] * t1[n * E_DIM + tid];
        aggS[tid] = ag;
    }
    if (tid >= 64 && tid < 96) {
        int l2 = tid - 64;
        float e = eaAll[l2];
        #pragma unroll
        for (int o = 16; o > 0; o >>= 1) e += __shfl_down_sync(0xffffffffu, e, o);
        if (l2 == 0) sS1 = e;
    }
    __syncthreads();
    if (tid < E_DIM) aggS[tid] /= sS1;
    __syncthreads();

    // ---- hop-1 epilogue ----
    #pragma unroll
    for (int k = 0; k < 8; k++) {
        int o = w * 8 + k;
        float2 wv = ((const float2*)(wxw + o * E_DIM))[lane];
        float p = wv.x * aggS[lane * 2] + wv.y * aggS[lane * 2 + 1];
        #pragma unroll
        for (int off = 16; off > 0; off >>= 1) p += __shfl_down_sync(0xffffffffu, p, off);
        if (lane == 0) vS[o] = leaky(p + wxb[o]);
    }
    __syncthreads();
    #pragma unroll
    for (int k = 0; k < 8; k++) {
        int o = w * 8 + k;
        float4 wv = ((const float4*)(wcw + o * 128))[lane];
        int i0 = lane * 4;
        float x0 = (i0 < 64)     ? hS[i0]     : vS[i0 - 64];
        float x1 = (i0 + 1 < 64) ? hS[i0 + 1] : vS[i0 - 63];
        float x2 = (i0 + 2 < 64) ? hS[i0 + 2] : vS[i0 - 62];
        float x3 = (i0 + 3 < 64) ? hS[i0 + 3] : vS[i0 - 61];
        float p = wv.x * x0 + wv.y * x1 + wv.z * x2 + wv.w * x3;
        #pragma unroll
        for (int off = 16; off > 0; off >>= 1) p += __shfl_down_sync(0xffffffffu, p, off);
        if (lane == 0) out[b * 192 + 64 + o] = leaky(p + wcb[o]);
    }
    if (tid < E_DIM) out[b * 192 + 128 + tid] = hS[tid];
    __syncthreads();

    // ---- hop-2 epilogue ----
    if (tid < E_DIM) {
        float s = 0.f;
        #pragma unroll
        for (int r = 0; r < 16; r++) s += part[r * 68 + tid];
        aggS[tid] = s / sS2;
    }
    __syncthreads();
    #pragma unroll
    for (int k = 0; k < 8; k++) {
        int o = w * 8 + k;
        float2 wv = ((const float2*)(wxw + o * E_DIM))[lane];
        float p = wv.x * aggS[lane * 2] + wv.y * aggS[lane * 2 + 1];
        #pragma unroll
        for (int off = 16; off > 0; off >>= 1) p += __shfl_down_sync(0xffffffffu, p, off);
        if (lane == 0) vS[o] = leaky(p + wxb[o]);
    }
    __syncthreads();
    #pragma unroll
    for (int k = 0; k < 8; k++) {
        int o = w * 8 + k;
        float4 wv = ((const float4*)(wcw + o * 128))[lane];
        int i0 = lane * 4;
        float x0 = (i0 < 64)     ? hsumS[i0]     : vS[i0 - 64];
        float x1 = (i0 + 1 < 64) ? hsumS[i0 + 1] : vS[i0 - 63];
        float x2 = (i0 + 2 < 64) ? hsumS[i0 + 2] : vS[i0 - 62];
        float x3 = (i0 + 3 < 64) ? hsumS[i0 + 3] : vS[i0 - 61];
        float p = wv.x * x0 + wv.y * x1 + wv.z * x2 + wv.w * x3;
        #pragma unroll
        for (int off = 16; off > 0; off >>= 1) p += __shfl_down_sync(0xffffffffu, p, off);
        if (lane == 0) out[b * 192 + o] = leaky(p + wcb[o]);
    }
}

// ---------------------------------------------------------------------------
extern "C" void kernel_launch(void* const* d_in, const int* in_sizes, int n_in,
                              void* d_out, int out_size) {
    const int*   entity_idx = (const int*)d_in[0];
    const int*   adj_e      = (const int*)d_in[1];
    const int*   adj_r      = (const int*)d_in[2];
    const float* E          = (const float*)d_in[3];
    const float* R          = (const float*)d_in[4];
    const float* w1         = (const float*)d_in[5];
    const float* w2         = (const float*)d_in[6];
    const float* w3         = (const float*)d_in[7];
    const float* wxw        = (const float*)d_in[8];
    const float* wxb        = (const float*)d_in[9];
    const float* wcw        = (const float*)d_in[10];
    const float* wcb        = (const float*)d_in[11];
    float* out = (float*)d_out;

    prep_kernel<<<NB_NORM + 1, 256>>>(E, R, w1, w2);
    fused_kernel<<<BSZ, 256>>>(entity_idx, adj_e, adj_r, E, w1, w3,
                               wxw, wxb, wcw, wcb, out);
}

// round 9
// speedup vs baseline: 1.3646x; 1.0461x over previous
#include <cuda_runtime.h>
#include <math.h>

#define N_ENT 100000
#define N_REL 64
#define E_DIM 64
#define KNB   32
#define BSZ   1024

typedef unsigned long long ull;

// Device scratch (no allocation allowed)
__device__ float  d_scale[N_ENT];            // per-entity normalization scale
__device__ float  d_RW[N_REL * E_DIM];       // RW[rel][f] = Rnorm[rel] . w1r[f]
__device__ float2 d_W2P[E_DIM * 32];         // d_W2P[f*32+q] = (w2[q][f], w2[q+32][f])

__device__ __forceinline__ float leaky(float x) { return x >= 0.f ? x : 0.2f * x; }

__device__ __forceinline__ ull ffma2(ull a, ull b, ull c) {
    ull d;
    asm("fma.rn.f32x2 %0, %1, %2, %3;" : "=l"(d) : "l"(a), "l"(b), "l"(c));
    return d;
}
__device__ __forceinline__ ull packdup(float x) {
    ull d;
    asm("mov.b64 %0, {%1, %1};" : "=l"(d) : "f"(x));
    return d;
}

// ---------------------------------------------------------------------------
// prep kernel: blocks [0, NB_NORM) compute per-entity scales with 4-row ILP;
// last block normalizes R, builds RW and pre-pairs W2.
// ---------------------------------------------------------------------------
#define ROWS_PER_BLK 64
#define NB_NORM ((N_ENT + ROWS_PER_BLK - 1) / ROWS_PER_BLK)

__global__ void __launch_bounds__(256) prep_kernel(const float* __restrict__ E,
                                                   const float* __restrict__ R,
                                                   const float* __restrict__ w1,
                                                   const float* __restrict__ w2) {
    int tid = threadIdx.x, w = tid >> 5, lane = tid & 31;

    if (blockIdx.x < NB_NORM) {
        int l = tid & 15;
        int rg = tid >> 4;
        int r0 = blockIdx.x * ROWS_PER_BLK + rg;
        float s[4] = {0.f, 0.f, 0.f, 0.f};
        #pragma unroll
        for (int k = 0; k < 4; k++) {
            int row = r0 + k * 16;
            if (row < N_ENT) {
                float4 v = ((const float4*)(E + (size_t)row * E_DIM))[l];
                s[k] = v.x * v.x + v.y * v.y + v.z * v.z + v.w * v.w;
            }
        }
        #pragma unroll
        for (int o = 8; o > 0; o >>= 1)
            #pragma unroll
            for (int k = 0; k < 4; k++) s[k] += __shfl_xor_sync(0xffffffffu, s[k], o);
        if (l == 0) {
            #pragma unroll
            for (int k = 0; k < 4; k++) {
                int row = r0 + k * 16;
                if (row < N_ENT) {
                    float n = sqrtf(s[k]);
                    d_scale[row] = (n > 1.0f) ? 1.0f / (n + 1e-7f) : 1.0f;
                }
            }
        }
        return;
    }

    // ---- prepRW block ----
    __shared__ float Rn[N_REL * E_DIM];       // 16 KB
    __shared__ float w1rT[E_DIM * 65];
    #pragma unroll
    for (int k = 0; k < 8; k++) {
        int row = w * 8 + k;
        float2 v = ((const float2*)(R + row * E_DIM))[lane];
        float ss = v.x * v.x + v.y * v.y;
        #pragma unroll
        for (int o = 16; o > 0; o >>= 1) ss += __shfl_xor_sync(0xffffffffu, ss, o);
        float n = sqrtf(ss);
        float sc = (n > 1.0f) ? 1.0f / (n + 1e-7f) : 1.0f;
        Rn[row * E_DIM + lane * 2]     = v.x * sc;
        Rn[row * E_DIM + lane * 2 + 1] = v.y * sc;
    }
    for (int i = tid; i < E_DIM * E_DIM; i += 256) {
        int f = i >> 6, e = i & 63;
        w1rT[e * 65 + f] = w1[f * 128 + 64 + e];
    }
    #pragma unroll
    for (int j = 0; j < 8; j++) {
        int i = tid + j * 256;               // i = f*32+q
        int f = i >> 5, q = i & 31;
        d_W2P[i] = make_float2(w2[q * E_DIM + f], w2[(q + 32) * E_DIM + f]);
    }
    __syncthreads();
    #pragma unroll
    for (int j = 0; j < 16; j++) {
        int i = tid + j * 256;
        int rel = i >> 6, f = i & 63;
        float s = 0.f;
        #pragma unroll
        for (int e = 0; e < E_DIM; e++) s += Rn[rel * E_DIM + e] * w1rT[e * 65 + f];
        d_RW[rel * E_DIM + f] = s;
    }
}

// ---------------------------------------------------------------------------
// Fused per-root kernel. One block (256 threads) per root.
// Entries: 0..31 = hop-1 neighbors (query hWh), 32..95 = hop-2 rels (hWs).
// big[] union (ordered by __syncthreads):
//   hidAll [0..6208) pitch 97
//   -> scoreP [0..768)
//   -> comb (float2) [768..2816) + aggP [2816..3360) + part [3360..4448)
// ---------------------------------------------------------------------------
__global__ void __launch_bounds__(256, 4) fused_kernel(
        const int* __restrict__ entity_idx,
        const int* __restrict__ adj_e,
        const int* __restrict__ adj_r,
        const float* __restrict__ E,
        const float* __restrict__ w1,
        const float* __restrict__ w3,
        const float* __restrict__ wxw,
        const float* __restrict__ wxb,
        const float* __restrict__ wcw,
        const float* __restrict__ wcb,
        float* __restrict__ out) {
    int b = blockIdx.x;
    int tid = threadIdx.x, w = tid >> 5, lane = tid & 31;

    __shared__ float  t1[KNB * E_DIM];          // 8 KB
    __shared__ int    idx2[KNB * KNB];          // 4 KB: idx | (rel<<20)
    __shared__ float  big[6208];                // 24.8 KB union
    __shared__ float  eaAll[96];
    __shared__ float  hS[E_DIM], hsumS[E_DIM];
    __shared__ float  hWh[E_DIM], hWs[E_DIM];
    __shared__ float  aggS[E_DIM], vS[E_DIM];
    __shared__ int    ent1[KNB], rel1[KNB];
    __shared__ float  red8[8];
    __shared__ float  sS1, sS2;

    float*  hidAll = big;                       // [0..6208), pitch 97
    float*  scoreP = big;                       // [0..768), 8*96
    float2* combV  = (float2*)(big + 768);      // [768..2816), 1024 float2
    float*  aggP   = big + 2816;                // [2816..3360), 8*68
    float*  part   = big + 3360;                // [3360..4448), 16*68

    int eidx = entity_idx[b];
    // ---- Phase A: root loads ----
    if (tid < KNB) {
        ent1[tid] = adj_e[eidx * KNB + tid];
        rel1[tid] = adj_r[eidx * KNB + tid];
    }
    if (tid < E_DIM) hS[tid] = E[(size_t)eidx * E_DIM + tid] * __ldg(&d_scale[eidx]);
    __syncthreads();

    // ---- Phase B: hop-2 packed indices + normalized t1 rows ----
    for (int i = tid; i < KNB * KNB; i += 256) {
        int e1 = ent1[i >> 5];
        int id = adj_e[e1 * KNB + (i & 31)];
        int rl = adj_r[e1 * KNB + (i & 31)];
        idx2[i] = id | (rl << 20);
    }
    for (int i = tid; i < KNB * E_DIM; i += 256) {
        int n = i >> 6, e = i & 63;
        int id = ent1[n];
        t1[i] = E[(size_t)id * E_DIM + e] * __ldg(&d_scale[id]);
    }
    __syncthreads();

    // ---- hsum ----
    if (tid < E_DIM) {
        float s = 0.f;
        #pragma unroll
        for (int n = 0; n < KNB; n++) s += t1[n * E_DIM + tid];
        hsumS[tid] = s;
    }
    __syncthreads();

    // ---- query projections ----
    #pragma unroll
    for (int k = 0; k < 16; k++) {
        int job = w * 16 + k;
        int f = job & 63;
        const float* q = (job < 64) ? hS : hsumS;
        float2 wv = ((const float2*)(w1 + f * 128))[lane];
        float p = wv.x * q[lane * 2] + wv.y * q[lane * 2 + 1];
        #pragma unroll
        for (int o = 16; o > 0; o >>= 1) p += __shfl_down_sync(0xffffffffu, p, o);
        if (lane == 0) { if (job < 64) hWh[f] = p; else hWs[f] = p; }
    }
    __syncthreads();

    // ---- stage hidAll via float4 RW loads ----
    {
        const float4* RW4 = (const float4*)d_RW;
        #pragma unroll
        for (int j = 0; j < 6; j++) {
            int job = j * 256 + tid;
            int entry = job >> 4, seg = job & 15;
            int rel = (entry < KNB) ? rel1[entry] : (entry - KNB);
            const float* qv = (entry < KNB) ? hWh : hWs;
            float4 rw = __ldg(&RW4[rel * 16 + seg]);
            int f0 = seg * 4;
            float x0 = qv[f0]     + rw.x;
            float x1 = qv[f0 + 1] + rw.y;
            float x2 = qv[f0 + 2] + rw.z;
            float x3 = qv[f0 + 3] + rw.w;
            hidAll[(f0)     * 97 + entry] = x0 > 0.f ? x0 : 0.f;
            hidAll[(f0 + 1) * 97 + entry] = x1 > 0.f ? x1 : 0.f;
            hidAll[(f0 + 2) * 97 + entry] = x2 > 0.f ? x2 : 0.f;
            hidAll[(f0 + 3) * 97 + entry] = x3 > 0.f ? x3 : 0.f;
        }
    }
    __syncthreads();

    // ---- score GEMM: single pass, 12 packed accums, W2 via 2x LDG.128/f ----
    float sPart0, sPart1, sPart2;
    {
        ull a[12];
        #pragma unroll
        for (int i = 0; i < 12; i++) a[i] = 0ull;
        const ulonglong2* W2q = (const ulonglong2*)d_W2P;  // [f*16 + q/2]
        int e0 = lane * 3;
        #pragma unroll 8
        for (int f = 0; f < E_DIM; f++) {
            ulonglong2 wab = __ldg(&W2q[f * 16 + w * 2]);
            ull h0 = packdup(hidAll[f * 97 + e0]);
            ull h1 = packdup(hidAll[f * 97 + e0 + 1]);
            ull h2 = packdup(hidAll[f * 97 + e0 + 2]);
            a[0]  = ffma2(wab.x, h0, a[0]);
            a[1]  = ffma2(wab.x, h1, a[1]);
            a[2]  = ffma2(wab.x, h2, a[2]);
            a[3]  = ffma2(wab.y, h0, a[3]);
            a[4]  = ffma2(wab.y, h1, a[4]);
            a[5]  = ffma2(wab.y, h2, a[5]);
            ulonglong2 wcd = __ldg(&W2q[f * 16 + w * 2 + 1]);
            a[6]  = ffma2(wcd.x, h0, a[6]);
            a[7]  = ffma2(wcd.x, h1, a[7]);
            a[8]  = ffma2(wcd.x, h2, a[8]);
            a[9]  = ffma2(wcd.y, h0, a[9]);
            a[10] = ffma2(wcd.y, h1, a[10]);
            a[11] = ffma2(wcd.y, h2, a[11]);
        }
        float w3v[4], w3u[4];
        #pragma unroll
        for (int q = 0; q < 4; q++) {
            int o = w * 4 + q;
            w3v[q] = __ldg(&w3[o]);
            w3u[q] = __ldg(&w3[o + 32]);
        }
        float sp[3];
        #pragma unroll
        for (int j = 0; j < 3; j++) {
            float s = 0.f;
            #pragma unroll
            for (int q = 0; q < 4; q++) {
                ull av = a[q * 3 + j];
                float g0 = __uint_as_float((unsigned)(av & 0xffffffffull));
                float g1 = __uint_as_float((unsigned)(av >> 32));
                g0 = g0 > 0.f ? g0 : 0.f;
                g1 = g1 > 0.f ? g1 : 0.f;
                s += w3v[q] * g0 + w3u[q] * g1;
            }
            sp[j] = s;
        }
        sPart0 = sp[0]; sPart1 = sp[1]; sPart2 = sp[2];
    }
    __syncthreads();   // hidAll dead
    {
        int e0 = lane * 3;
        scoreP[w * 96 + e0]     = sPart0;
        scoreP[w * 96 + e0 + 1] = sPart1;
        scoreP[w * 96 + e0 + 2] = sPart2;
    }
    __syncthreads();
    if (tid < 96) {
        float c = 0.f;
        #pragma unroll
        for (int ww = 0; ww < 8; ww++) c += scoreP[ww * 96 + tid];
        eaAll[tid] = expf(1.f / (1.f + expf(-c)));
    }
    __syncthreads();

    // ---- comb pack: (idx_bits, ea*scale) per neighbor; S2 partials; sS1 ----
    {
        float sp = 0.f;
        #pragma unroll
        for (int j = 0; j < 4; j++) {
            int i = tid * 4 + j;
            int v = idx2[i];
            int rl = v >> 20, id = v & 0xFFFFF;
            float ea = eaAll[32 + rl];
            combV[i] = make_float2(__int_as_float(id), ea * __ldg(&d_scale[id]));
            sp += ea;
        }
        #pragma unroll
        for (int o = 16; o > 0; o >>= 1) sp += __shfl_down_sync(0xffffffffu, sp, o);
        if (lane == 0) red8[w] = sp;
        if (w == 0) {   // hop-1 softmax denominator in parallel
            float e1v = eaAll[lane];
            #pragma unroll
            for (int o = 16; o > 0; o >>= 1) e1v += __shfl_down_sync(0xffffffffu, e1v, o);
            if (lane == 0) sS1 = e1v;
        }
    }
    __syncthreads();
    if (tid == 0) {
        float s = 0.f;
        #pragma unroll
        for (int i = 0; i < 8; i++) s += red8[i];
        sS2 = s;
    }

    // ---- hop-2 weighted gather: 1 LDS.64 + 1 LDG.128 + 4 FMA per neighbor ----
    {
        const float4* E4 = (const float4*)E;
        int seg = tid & 15, r = tid >> 4;
        float4 gacc = make_float4(0.f, 0.f, 0.f, 0.f);
        #pragma unroll
        for (int base = 0; base < KNB * KNB; base += 64) {
            float2 cs[4];
            float4 vs[4];
            #pragma unroll
            for (int u4 = 0; u4 < 4; u4++)
                cs[u4] = combV[base + u4 * 16 + r];
            #pragma unroll
            for (int u4 = 0; u4 < 4; u4++)
                vs[u4] = __ldg(&E4[(size_t)__float_as_int(cs[u4].x) * 16 + seg]);
            #pragma unroll
            for (int u4 = 0; u4 < 4; u4++) {
                float wv = cs[u4].y;
                gacc.x += wv * vs[u4].x; gacc.y += wv * vs[u4].y;
                gacc.z += wv * vs[u4].z; gacc.w += wv * vs[u4].w;
            }
        }
        ((float4*)(part + r * 68))[seg] = gacc;
    }

    // ---- hop-1 aggregation partials: all 8 warps, 4 neighbors each ----
    {
        float a0 = 0.f, a1 = 0.f;
        #pragma unroll
        for (int k = 0; k < 4; k++) {
            int n = w * 4 + k;
            float ea = eaAll[n];
            a0 += ea * t1[n * E_DIM + lane];
            a1 += ea * t1[n * E_DIM + lane + 32];
        }
        aggP[w * 68 + lane]      = a0;
        aggP[w * 68 + lane + 32] = a1;
    }
    __syncthreads();
    if (tid < E_DIM) {
        float s = 0.f;
        #pragma unroll
        for (int ww = 0; ww < 8; ww++) s += aggP[ww * 68 + tid];
        aggS[tid] = s / sS1;
    }
    __syncthreads();

    // ---- hop-1 epilogue ----
    #pragma unroll
    for (int k = 0; k < 8; k++) {
        int o = w * 8 + k;
        float2 wv = ((const float2*)(wxw + o * E_DIM))[lane];
        float p = wv.x * aggS[lane * 2] + wv.y * aggS[lane * 2 + 1];
        #pragma unroll
        for (int off = 16; off > 0; off >>= 1) p += __shfl_down_sync(0xffffffffu, p, off);
        if (lane == 0) vS[o] = leaky(p + wxb[o]);
    }
    __syncthreads();
    #pragma unroll
    for (int k = 0; k < 8; k++) {
        int o = w * 8 + k;
        float4 wv = ((const float4*)(wcw + o * 128))[lane];
        int i0 = lane * 4;
        float x0 = (i0 < 64)     ? hS[i0]     : vS[i0 - 64];
        float x1 = (i0 + 1 < 64) ? hS[i0 + 1] : vS[i0 - 63];
        float x2 = (i0 + 2 < 64) ? hS[i0 + 2] : vS[i0 - 62];
        float x3 = (i0 + 3 < 64) ? hS[i0 + 3] : vS[i0 - 61];
        float p = wv.x * x0 + wv.y * x1 + wv.z * x2 + wv.w * x3;
        #pragma unroll
        for (int off = 16; off > 0; off >>= 1) p += __shfl_down_sync(0xffffffffu, p, off);
        if (lane == 0) out[b * 192 + 64 + o] = leaky(p + wcb[o]);
    }
    if (tid < E_DIM) out[b * 192 + 128 + tid] = hS[tid];
    __syncthreads();

    // ---- hop-2 epilogue ----
    if (tid < E_DIM) {
        float s = 0.f;
        #pragma unroll
        for (int r = 0; r < 16; r++) s += part[r * 68 + tid];
        aggS[tid] = s / sS2;
    }
    __syncthreads();
    #pragma unroll
    for (int k = 0; k < 8; k++) {
        int o = w * 8 + k;
        float2 wv = ((const float2*)(wxw + o * E_DIM))[lane];
        float p = wv.x * aggS[lane * 2] + wv.y * aggS[lane * 2 + 1];
        #pragma unroll
        for (int off = 16; off > 0; off >>= 1) p += __shfl_down_sync(0xffffffffu, p, off);
        if (lane == 0) vS[o] = leaky(p + wxb[o]);
    }
    __syncthreads();
    #pragma unroll
    for (int k = 0; k < 8; k++) {
        int o = w * 8 + k;
        float4 wv = ((const float4*)(wcw + o * 128))[lane];
        int i0 = lane * 4;
        float x0 = (i0 < 64)     ? hsumS[i0]     : vS[i0 - 64];
        float x1 = (i0 + 1 < 64) ? hsumS[i0 + 1] : vS[i0 - 63];
        float x2 = (i0 + 2 < 64) ? hsumS[i0 + 2] : vS[i0 - 62];
        float x3 = (i0 + 3 < 64) ? hsumS[i0 + 3] : vS[i0 - 61];
        float p = wv.x * x0 + wv.y * x1 + wv.z * x2 + wv.w * x3;
        #pragma unroll
        for (int off = 16; off > 0; off >>= 1) p += __shfl_down_sync(0xffffffffu, p, off);
        if (lane == 0) out[b * 192 + o] = leaky(p + wcb[o]);
    }
}

// ---------------------------------------------------------------------------
extern "C" void kernel_launch(void* const* d_in, const int* in_sizes, int n_in,
                              void* d_out, int out_size) {
    const int*   entity_idx = (const int*)d_in[0];
    const int*   adj_e      = (const int*)d_in[1];
    const int*   adj_r      = (const int*)d_in[2];
    const float* E          = (const float*)d_in[3];
    const float* R          = (const float*)d_in[4];
    const float* w1         = (const float*)d_in[5];
    const float* w2         = (const float*)d_in[6];
    const float* w3         = (const float*)d_in[7];
    const float* wxw        = (const float*)d_in[8];
    const float* wxb        = (const float*)d_in[9];
    const float* wcw        = (const float*)d_in[10];
    const float* wcb        = (const float*)d_in[11];
    float* out = (float*)d_out;

    prep_kernel<<<NB_NORM + 1, 256>>>(E, R, w1, w2);
    fused_kernel<<<BSZ, 256>>>(entity_idx, adj_e, adj_r, E, w1, w3,
                               wxw, wxb, wcw, wcb, out);
}